// round 8
// baseline (speedup 1.0000x reference)
#include <cuda_runtime.h>
#include <cuda_fp16.h>
#include <mma.h>
#include <cstdint>

using namespace nvcuda;

#define NODES_MAX 50000
#define DDIM 256          // input feature dim
#define ADIM 128          // attention dim (q or k width)
#define QKW 256           // concat width: [q | k]
#define MBLK 64           // GEMM m-block rows
#define NSTRIPS 148       // persistent m-strips (one per SM)

// fp16 scratch tables
__device__ __half g_qk[(size_t)NODES_MAX * QKW];   // output of GEMM: [q|k] per node
__device__ __half g_xh[(size_t)NODES_MAX * DDIM];  // fp16 copy of x
__device__ __half g_wh[(size_t)QKW * DDIM];        // fp16 [Wq ; Wk]

// ---------------------------------------------------------------------------
// Kernel 0: fp32 -> fp16 convert for x and W (pure streaming)
// ---------------------------------------------------------------------------
__global__ __launch_bounds__(256)
void convert_kernel(const float* __restrict__ x,
                    const float* __restrict__ Wq,
                    const float* __restrict__ Wk,
                    int nx4, int nw4h)
{
    int i = blockIdx.x * blockDim.x + threadIdx.x;
    const int total = nx4 + 2 * nw4h;
    if (i >= total) return;
    float4 v;
    __half* dst;
    if (i < nx4) {
        v = reinterpret_cast<const float4*>(x)[i];
        dst = g_xh + (size_t)i * 4;
    } else {
        int w = i - nx4;
        v = (w < nw4h) ? reinterpret_cast<const float4*>(Wq)[w]
                       : reinterpret_cast<const float4*>(Wk)[w - nw4h];
        dst = g_wh + (size_t)w * 4;
    }
    __half2 h0 = __floats2half2_rn(v.x, v.y);
    __half2 h1 = __floats2half2_rn(v.z, v.w);
    uint2 pk;
    pk.x = *reinterpret_cast<unsigned int*>(&h0);
    pk.y = *reinterpret_cast<unsigned int*>(&h1);
    *reinterpret_cast<uint2*>(dst) = pk;
}

// ---------------------------------------------------------------------------
// cp.async helpers
// ---------------------------------------------------------------------------
__device__ __forceinline__ void cp16(void* dst, const void* src, bool pred) {
    unsigned sa = (unsigned)__cvta_generic_to_shared(dst);
    int sz = pred ? 16 : 0;
    asm volatile("cp.async.cg.shared.global [%0], [%1], 16, %2;\n"
                 :: "r"(sa), "l"(src), "r"(sz));
}
__device__ __forceinline__ void cp_commit() {
    asm volatile("cp.async.commit_group;\n");
}
template <int W>
__device__ __forceinline__ void cp_wait() {
    asm volatile("cp.async.wait_group %0;\n" :: "n"(W));
}

// ---------------------------------------------------------------------------
// Kernel 1: persistent projection GEMM with W-quarter resident in smem.
// Grid = 4 n-quarters x 148 strips. Block = 256 (8 warps: 2m x 4n).
// Each CTA: load W rows [qn*64, qn*64+64) once (fp16, ldm 264 padded),
// then for each m-block (strip, strip+148, ...): 3-stage cp.async A tiles
// (BK=16, 16 k-iters), wmma m16n16k16, epilogue bias+fp16 store.
// smem: Ws 33792B + As 9216B = 43008B (epilogue f32 staging aliases As).
// ---------------------------------------------------------------------------
#define WLDM 264          // Ws leading dim (halves), 264 % 8 == 0
#define ALDM 24           // As leading dim (halves), 24 % 8 == 0
#define KIT  (DDIM / 16)  // 16 k-iters

__global__ __launch_bounds__(256)
void gemm_qk_persist(const float* __restrict__ bq,
                     const float* __restrict__ bk,
                     int N, int mblocks)
{
    __shared__ __align__(16) __half Ws[64][WLDM];       // 33792 B
    __shared__ __align__(16) __half As[3][MBLK][ALDM];  // 9216 B

    const int tid  = threadIdx.x;
    const int wid  = tid >> 5;
    const int lane = tid & 31;
    const int qn    = blockIdx.x & 3;     // n-quarter: j in [qn*64, qn*64+64)
    const int strip = blockIdx.x >> 2;    // m-strip
    const int j0    = qn * 64;

    const int wm = wid & 1;               // m offset wm*32
    const int wn = wid >> 1;              // n offset wn*16 (within quarter)

    // ---- load W quarter into smem (once) ----
    {
        const int row = tid >> 2;                 // 0..63
        const int cbase = (tid & 3) * 64;         // halves
        const __half* src = g_wh + (size_t)(j0 + row) * DDIM + cbase;
        #pragma unroll
        for (int cc = 0; cc < 8; cc++) {
            int col = cbase + cc * 8;
            *reinterpret_cast<uint4*>(&Ws[row][col]) =
                *reinterpret_cast<const uint4*>(src + cc * 8);
        }
    }
    __syncthreads();

    // A staging map: threads 0..127, one 16B chunk per stage
    const int arow = tid >> 1;            // 0..127 -> row (only <64 valid via mask)
    const int aoff = (tid & 1) * 8;       // halves: 0 or 8
    const bool aload = tid < 128;

    // bias for this warp's 16 j-columns, per-lane precompute (j = j0+wn*16+ecg+t)
    const int erow = lane & 15;
    const int ecg  = (lane >> 4) * 8;

    for (int mb = strip; mb < mblocks; mb += NSTRIPS) {
        const int m0 = mb * MBLK;
        const int gm = m0 + arow;
        const bool mok = aload && (gm < N) && (arow < MBLK);
        const __half* asrc = g_xh + (size_t)gm * DDIM + aoff;

        wmma::fragment<wmma::accumulator, 16, 16, 16, float> c[2];
        wmma::fill_fragment(c[0], 0.0f);
        wmma::fill_fragment(c[1], 0.0f);

        // prologue: stages 0,1
        #pragma unroll
        for (int s = 0; s < 2; s++) {
            if (aload) cp16(&As[s][arow][aoff], asrc + s * 16, mok);
            cp_commit();
        }

        #pragma unroll
        for (int it = 0; it < KIT; it++) {
            const int buf = it % 3;
            if (it == KIT - 1) cp_wait<0>(); else cp_wait<1>();
            __syncthreads();

            const int kn = (it + 2) * 16;
            if (kn < DDIM) {
                const int nbuf = (it + 2) % 3;
                if (aload) cp16(&As[nbuf][arow][aoff], asrc + kn, mok);
                cp_commit();
            }

            wmma::fragment<wmma::matrix_a, 16, 16, 16, __half, wmma::row_major> a[2];
            wmma::fragment<wmma::matrix_b, 16, 16, 16, __half, wmma::col_major> b;
            wmma::load_matrix_sync(a[0], &As[buf][wm * 32][0], ALDM);
            wmma::load_matrix_sync(a[1], &As[buf][wm * 32 + 16][0], ALDM);
            wmma::load_matrix_sync(b, &Ws[wn * 16][it * 16], WLDM);
            wmma::mma_sync(c[0], a[0], b, c[0]);
            wmma::mma_sync(c[1], a[1], b, c[1]);
        }
        __syncthreads();   // all A reads done; epilogue staging aliases As

        // epilogue: per-warp 1KB f32 staging in As region
        float* epw = reinterpret_cast<float*>(&As[0][0][0]) + wid * 256;
        #pragma unroll
        for (int i = 0; i < 2; i++) {
            wmma::store_matrix_sync(epw, c[i], 16, wmma::mem_row_major);
            __syncwarp();
            int gmm = m0 + wm * 32 + i * 16 + erow;
            int gj0 = j0 + wn * 16 + ecg;
            if (gmm < N) {
                __half hv[8];
                #pragma unroll
                for (int t = 0; t < 8; t++) {
                    int gj = gj0 + t;
                    float bias = (gj < ADIM) ? bq[gj] : bk[gj - ADIM];
                    hv[t] = __float2half(epw[erow * 16 + ecg + t] + bias);
                }
                *reinterpret_cast<uint4*>(g_qk + (size_t)gmm * QKW + gj0) =
                    *reinterpret_cast<const uint4*>(hv);
            }
            __syncwarp();
        }
        __syncthreads();   // epilogue reads done before next m-block prologue
    }
}

// ---------------------------------------------------------------------------
// Kernel 2: per-edge symmetric attention score + fused scatter-add.
// 8 lanes per edge, 4 edges per warp (unchanged).
// ---------------------------------------------------------------------------
__global__ __launch_bounds__(256)
void edge_kernel(const int* __restrict__ ei,     // [2, E]
                 const int* __restrict__ d0r1,   // d0_index row 1, [2E]
                 float* __restrict__ out,
                 int N, int E)
{
    const int warp = (blockIdx.x * blockDim.x + threadIdx.x) >> 5;
    const int lane = threadIdx.x & 31;
    const int g    = lane >> 3;
    const int l    = lane & 7;
    const int e    = warp * 4 + g;
    if (e >= E) return;

    const int s = __ldg(ei + e);
    const int d = __ldg(ei + E + e);

    const uint4* rs = reinterpret_cast<const uint4*>(g_qk + (size_t)s * QKW);
    const uint4* rd = reinterpret_cast<const uint4*>(g_qk + (size_t)d * QKW);

    const uint4 a0 = rs[l];        const uint4 b0 = rd[16 + l];
    const uint4 a1 = rs[8 + l];    const uint4 b1 = rd[24 + l];
    const uint4 a2 = rd[l];        const uint4 b2 = rs[16 + l];
    const uint4 a3 = rd[8 + l];    const uint4 b3 = rs[24 + l];

    float p = 0.f;
    {
        const __half2* ah; const __half2* bh;
        #define DOT8(AV, BV)                                         \
            ah = reinterpret_cast<const __half2*>(&(AV));            \
            bh = reinterpret_cast<const __half2*>(&(BV));            \
            _Pragma("unroll")                                        \
            for (int i = 0; i < 4; i++) {                            \
                float2 fa = __half22float2(ah[i]);                   \
                float2 fb = __half22float2(bh[i]);                   \
                p = fmaf(fa.x, fb.x, p);                             \
                p = fmaf(fa.y, fb.y, p);                             \
            }
        DOT8(a0, b0)
        DOT8(a1, b1)
        DOT8(a2, b2)
        DOT8(a3, b3)
        #undef DOT8
    }

    p += __shfl_xor_sync(0xffffffffu, p, 4);
    p += __shfl_xor_sync(0xffffffffu, p, 2);
    p += __shfl_xor_sync(0xffffffffu, p, 1);

    if (l == 0) {
        const float v = __expf(p * 0.0625f);
        out[N + e] = v;
        int2 dp = *reinterpret_cast<const int2*>(d0r1 + 2 * e);
        atomicAdd(out + dp.x, v);
        atomicAdd(out + dp.y, v);
    }
}

// ---------------------------------------------------------------------------
extern "C" void kernel_launch(void* const* d_in, const int* in_sizes, int n_in,
                              void* d_out, int out_size)
{
    const float* x  = (const float*)d_in[0];
    const float* Wq = (const float*)d_in[1];
    const float* bq = (const float*)d_in[2];
    const float* Wk = (const float*)d_in[3];
    const float* bk = (const float*)d_in[4];
    const int*   ei = (const int*)d_in[5];
    const int*   d0 = (const int*)d_in[6];
    float* out = (float*)d_out;

    const int A    = in_sizes[2];             // 128
    const int Dd   = in_sizes[1] / A;         // 256
    const int N    = in_sizes[0] / Dd;        // 50000
    const int E    = in_sizes[5] / 2;         // 800000
    const int twoE = in_sizes[6] / 2;         // 2E
    (void)n_in; (void)out_size;

    cudaMemsetAsync(out, 0, (size_t)N * sizeof(float), 0);

    // fp32 -> fp16 tables
    const int nx4  = N * (Dd / 4);
    const int nw4h = A * Dd / 4;
    int cblocks = (nx4 + 2 * nw4h + 255) / 256;
    convert_kernel<<<cblocks, 256>>>(x, Wq, Wk, nx4, nw4h);

    // persistent projection GEMM: 4 n-quarters x 148 strips
    const int mblocks = (N + MBLK - 1) / MBLK;
    gemm_qk_persist<<<4 * NSTRIPS, 256>>>(bq, bk, N, mblocks);

    // per-edge score + scatter
    int nwarps = (E + 3) / 4;
    int blocks = (nwarps + 7) / 8;
    edge_kernel<<<blocks, 256>>>(ei, d0 + twoE, out, N, E);
}

// round 10
// speedup vs baseline: 1.1371x; 1.1371x over previous
#include <cuda_runtime.h>
#include <cuda_fp16.h>
#include <cstdint>

#define NODES_MAX 50000
#define DDIM 256          // input feature dim
#define ADIM 128          // attention dim
#define QKW 256           // [q | k] width

// fp16 scratch tables
__device__ __half g_qk[(size_t)NODES_MAX * QKW];   // GEMM output
__device__ __half g_xh[(size_t)NODES_MAX * DDIM];  // fp16 x
__device__ __half g_wh[(size_t)QKW * DDIM];        // fp16 [Wq ; Wk]

// ---------------------------------------------------------------------------
// Kernel 0: fp32 -> fp16 convert (pure streaming)
// ---------------------------------------------------------------------------
__global__ __launch_bounds__(256)
void convert_kernel(const float* __restrict__ x,
                    const float* __restrict__ Wq,
                    const float* __restrict__ Wk,
                    int nx4, int nw4h)
{
    int i = blockIdx.x * blockDim.x + threadIdx.x;
    const int total = nx4 + 2 * nw4h;
    if (i >= total) return;
    float4 v;
    __half* dst;
    if (i < nx4) {
        v = reinterpret_cast<const float4*>(x)[i];
        dst = g_xh + (size_t)i * 4;
    } else {
        int w = i - nx4;
        v = (w < nw4h) ? reinterpret_cast<const float4*>(Wq)[w]
                       : reinterpret_cast<const float4*>(Wk)[w - nw4h];
        dst = g_wh + (size_t)w * 4;
    }
    __half2 h0 = __floats2half2_rn(v.x, v.y);
    __half2 h1 = __floats2half2_rn(v.z, v.w);
    uint2 pk;
    pk.x = *reinterpret_cast<unsigned int*>(&h0);
    pk.y = *reinterpret_cast<unsigned int*>(&h1);
    *reinterpret_cast<uint2*>(dst) = pk;
}

// ---------------------------------------------------------------------------
// Async-copy / ldmatrix / mma helpers (all baseline compute_103 PTX)
// ---------------------------------------------------------------------------
__device__ __forceinline__ void cp16(void* dst, const void* src, bool pred) {
    unsigned sa = (unsigned)__cvta_generic_to_shared(dst);
    int sz = pred ? 16 : 0;
    asm volatile("cp.async.cg.shared.global [%0], [%1], 16, %2;\n"
                 :: "r"(sa), "l"(src), "r"(sz));
}
__device__ __forceinline__ void cp_commit() { asm volatile("cp.async.commit_group;\n"); }
template <int W>
__device__ __forceinline__ void cp_wait() {
    asm volatile("cp.async.wait_group %0;\n" :: "n"(W));
}
__device__ __forceinline__ void ldsm_x4(uint32_t& r0, uint32_t& r1,
                                        uint32_t& r2, uint32_t& r3, uint32_t addr) {
    asm volatile("ldmatrix.sync.aligned.m8n8.x4.shared.b16 {%0,%1,%2,%3}, [%4];"
                 : "=r"(r0), "=r"(r1), "=r"(r2), "=r"(r3) : "r"(addr));
}
__device__ __forceinline__ void mma16816(float* c,
                                         uint32_t a0, uint32_t a1, uint32_t a2, uint32_t a3,
                                         uint32_t b0, uint32_t b1) {
    asm volatile("mma.sync.aligned.m16n8k16.row.col.f32.f16.f16.f32 "
                 "{%0,%1,%2,%3}, {%4,%5,%6,%7}, {%8,%9}, {%0,%1,%2,%3};"
                 : "+f"(c[0]), "+f"(c[1]), "+f"(c[2]), "+f"(c[3])
                 : "r"(a0), "r"(a1), "r"(a2), "r"(a3), "r"(b0), "r"(b1));
}

// ---------------------------------------------------------------------------
// Kernel 1: projection GEMM via mma.sync + ldmatrix.
//   qk[m][j] = sum_k xh[m][k] * wh[j][k] + b[j]
// BM=128, BN=128, BK=32, 256 threads, 8 warps (2m x 4n), warp tile 64x32.
// smem rows stride 40 halves (80B) -> ldmatrix conflict-free.
// 2-stage cp.async; tail iteration waits group 0 (race-safe).
// ---------------------------------------------------------------------------
#define LDM 40
#define KIT (DDIM / 32)   // 8

__global__ __launch_bounds__(256)
void gemm_qk_mma(const float* __restrict__ bq,
                 const float* __restrict__ bk,
                 int N)
{
    __shared__ __align__(16) __half As[2][128][LDM];   // 20480 B
    __shared__ __align__(16) __half Bs[2][128][LDM];   // 20480 B
    __shared__ float bias_s[128];

    const int tid  = threadIdx.x;
    const int wid  = tid >> 5;
    const int lane = tid & 31;
    const int m0   = blockIdx.x * 128;
    const int n0   = blockIdx.y * 128;

    const int wm = wid & 1;           // m offset wm*64
    const int wn = wid >> 1;          // n offset wn*32

    // bias for this block's 128 columns
    if (tid < 128) {
        int gj = n0 + tid;
        bias_s[tid] = (gj < ADIM) ? bq[gj] : bk[gj - ADIM];
    }

    float c[4][4][4];                 // [m-frag][n8-frag][quad]
    #pragma unroll
    for (int i = 0; i < 4; i++)
        #pragma unroll
        for (int j = 0; j < 4; j++)
            #pragma unroll
            for (int q = 0; q < 4; q++) c[i][j][q] = 0.f;

    // staging map: 512 16B-chunks per 128x32 tile, 2 per thread
    const int srow = tid >> 1;            // 0..127
    const int scol = (tid & 1) * 16;      // halves: 0 or 16
    const int gm   = m0 + srow;
    const bool mok = gm < N;
    const __half* asrc = g_xh + (size_t)gm * DDIM + scol;
    const __half* bsrc = g_wh + (size_t)(n0 + srow) * DDIM + scol;

    // ldmatrix per-lane base byte-offsets (within a stage)
    const uint32_t aoff = (uint32_t)(((wm * 64 + (lane & 15)) * LDM + (lane >> 4) * 8) * 2);
    const uint32_t boff = (uint32_t)(((wn * 32 + ((lane >> 3) & 1) * 8 + (lane & 7)) * LDM
                                      + (lane >> 4) * 8) * 2);
    const uint32_t smA0 = (uint32_t)__cvta_generic_to_shared(&As[0][0][0]);
    const uint32_t smB0 = (uint32_t)__cvta_generic_to_shared(&Bs[0][0][0]);
    const uint32_t stageA = 128 * LDM * 2;
    const uint32_t stageB = 128 * LDM * 2;

    // prologue: stages 0,1
    #pragma unroll
    for (int s = 0; s < 2; s++) {
        const int k0 = s * 32;
        cp16(&As[s][srow][scol],     asrc + k0,     mok);
        cp16(&As[s][srow][scol + 8], asrc + k0 + 8, mok);
        cp16(&Bs[s][srow][scol],     bsrc + k0,     true);
        cp16(&Bs[s][srow][scol + 8], bsrc + k0 + 8, true);
        cp_commit();
    }

    #pragma unroll
    for (int it = 0; it < KIT; it++) {
        const int buf = it & 1;
        if (it == KIT - 1) cp_wait<0>(); else cp_wait<1>();
        __syncthreads();

        const uint32_t abase = smA0 + buf * stageA + aoff;
        const uint32_t bbase = smB0 + buf * stageB + boff;

        #pragma unroll
        for (int ks = 0; ks < 32; ks += 16) {
            uint32_t a[4][4];
            #pragma unroll
            for (int i = 0; i < 4; i++)
                ldsm_x4(a[i][0], a[i][1], a[i][2], a[i][3],
                        abase + (uint32_t)((i * 16 * LDM + ks) * 2));
            uint32_t b0[4], b1[4];
            ldsm_x4(b0[0], b0[1], b0[2], b0[3], bbase + (uint32_t)(ks * 2));
            ldsm_x4(b1[0], b1[1], b1[2], b1[3], bbase + (uint32_t)((16 * LDM + ks) * 2));

            #pragma unroll
            for (int i = 0; i < 4; i++) {
                mma16816(c[i][0], a[i][0], a[i][1], a[i][2], a[i][3], b0[0], b0[2]);
                mma16816(c[i][1], a[i][0], a[i][1], a[i][2], a[i][3], b0[1], b0[3]);
                mma16816(c[i][2], a[i][0], a[i][1], a[i][2], a[i][3], b1[0], b1[2]);
                mma16816(c[i][3], a[i][0], a[i][1], a[i][2], a[i][3], b1[1], b1[3]);
            }
        }
        __syncthreads();

        const int kn = (it + 2) * 32;
        if (kn < DDIM) {
            cp16(&As[buf][srow][scol],     asrc + kn,     mok);
            cp16(&As[buf][srow][scol + 8], asrc + kn + 8, mok);
            cp16(&Bs[buf][srow][scol],     bsrc + kn,     true);
            cp16(&Bs[buf][srow][scol + 8], bsrc + kn + 8, true);
            cp_commit();
        }
    }

    // epilogue: direct gmem stores with bias (half2 per fragment row)
    const int colq = (lane & 3) * 2;               // 0,2,4,6
    #pragma unroll
    for (int j = 0; j < 4; j++) {
        const int col = n0 + wn * 32 + j * 8 + colq;
        const float bx = bias_s[col - n0];
        const float by = bias_s[col - n0 + 1];
        #pragma unroll
        for (int i = 0; i < 4; i++) {
            const int r0 = m0 + wm * 64 + i * 16 + (lane >> 2);
            if (r0 < N) {
                __half2 h = __floats2half2_rn(c[i][j][0] + bx, c[i][j][1] + by);
                *reinterpret_cast<__half2*>(g_qk + (size_t)r0 * QKW + col) = h;
            }
            const int r1 = r0 + 8;
            if (r1 < N) {
                __half2 h = __floats2half2_rn(c[i][j][2] + bx, c[i][j][3] + by);
                *reinterpret_cast<__half2*>(g_qk + (size_t)r1 * QKW + col) = h;
            }
        }
    }
}

// ---------------------------------------------------------------------------
// Kernel 2: per-edge symmetric attention score + fused scatter-add.
// 8 lanes per edge, 4 edges per warp (unchanged; at L2 cap).
// ---------------------------------------------------------------------------
__global__ __launch_bounds__(256)
void edge_kernel(const int* __restrict__ ei,
                 const int* __restrict__ d0r1,
                 float* __restrict__ out,
                 int N, int E)
{
    const int warp = (blockIdx.x * blockDim.x + threadIdx.x) >> 5;
    const int lane = threadIdx.x & 31;
    const int g    = lane >> 3;
    const int l    = lane & 7;
    const int e    = warp * 4 + g;
    if (e >= E) return;

    const int s = __ldg(ei + e);
    const int d = __ldg(ei + E + e);

    const uint4* rs = reinterpret_cast<const uint4*>(g_qk + (size_t)s * QKW);
    const uint4* rd = reinterpret_cast<const uint4*>(g_qk + (size_t)d * QKW);

    const uint4 a0 = rs[l];        const uint4 b0 = rd[16 + l];
    const uint4 a1 = rs[8 + l];    const uint4 b1 = rd[24 + l];
    const uint4 a2 = rd[l];        const uint4 b2 = rs[16 + l];
    const uint4 a3 = rd[8 + l];    const uint4 b3 = rs[24 + l];

    float p = 0.f;
    {
        const __half2* ah; const __half2* bh;
        #define DOT8(AV, BV)                                         \
            ah = reinterpret_cast<const __half2*>(&(AV));            \
            bh = reinterpret_cast<const __half2*>(&(BV));            \
            _Pragma("unroll")                                        \
            for (int i = 0; i < 4; i++) {                            \
                float2 fa = __half22float2(ah[i]);                   \
                float2 fb = __half22float2(bh[i]);                   \
                p = fmaf(fa.x, fb.x, p);                             \
                p = fmaf(fa.y, fb.y, p);                             \
            }
        DOT8(a0, b0)
        DOT8(a1, b1)
        DOT8(a2, b2)
        DOT8(a3, b3)
        #undef DOT8
    }

    p += __shfl_xor_sync(0xffffffffu, p, 4);
    p += __shfl_xor_sync(0xffffffffu, p, 2);
    p += __shfl_xor_sync(0xffffffffu, p, 1);

    if (l == 0) {
        const float v = __expf(p * 0.0625f);
        out[N + e] = v;
        int2 dp = *reinterpret_cast<const int2*>(d0r1 + 2 * e);
        atomicAdd(out + dp.x, v);
        atomicAdd(out + dp.y, v);
    }
}

// ---------------------------------------------------------------------------
extern "C" void kernel_launch(void* const* d_in, const int* in_sizes, int n_in,
                              void* d_out, int out_size)
{
    const float* x  = (const float*)d_in[0];
    const float* Wq = (const float*)d_in[1];
    const float* bq = (const float*)d_in[2];
    const float* Wk = (const float*)d_in[3];
    const float* bk = (const float*)d_in[4];
    const int*   ei = (const int*)d_in[5];
    const int*   d0 = (const int*)d_in[6];
    float* out = (float*)d_out;

    const int A    = in_sizes[2];             // 128
    const int Dd   = in_sizes[1] / A;         // 256
    const int N    = in_sizes[0] / Dd;        // 50000
    const int E    = in_sizes[5] / 2;         // 800000
    const int twoE = in_sizes[6] / 2;         // 2E
    (void)n_in; (void)out_size;

    cudaMemsetAsync(out, 0, (size_t)N * sizeof(float), 0);

    const int nx4  = N * (Dd / 4);
    const int nw4h = A * Dd / 4;
    int cblocks = (nx4 + 2 * nw4h + 255) / 256;
    convert_kernel<<<cblocks, 256>>>(x, Wq, Wk, nx4, nw4h);

    dim3 ggrd((N + 127) / 128, QKW / 128);
    gemm_qk_mma<<<ggrd, 256>>>(bq, bk, N);

    int nwarps = (E + 3) / 4;
    int blocks = (nwarps + 7) / 8;
    edge_kernel<<<blocks, 256>>>(ei, d0 + twoE, out, N, E);
}

// round 11
// speedup vs baseline: 1.1749x; 1.0333x over previous
#include <cuda_runtime.h>
#include <cuda_fp16.h>
#include <cstdint>

#define NODES_MAX 50000
#define DDIM 256          // input feature dim
#define ADIM 128          // attention dim
#define QKW 256           // [q | k] width

// fp16 scratch tables
__device__ __half g_qk[(size_t)NODES_MAX * QKW];   // GEMM output
__device__ __half g_wh[(size_t)QKW * DDIM];        // fp16 [Wq ; Wk]

// ---------------------------------------------------------------------------
// Kernel 0: fp32 -> fp16 convert for W only (tiny: 65536 float4 total)
// ---------------------------------------------------------------------------
__global__ __launch_bounds__(256)
void convert_w_kernel(const float* __restrict__ Wq,
                      const float* __restrict__ Wk,
                      int nw4h)     // float4 count of one W (=ADIM*DDIM/4)
{
    int i = blockIdx.x * blockDim.x + threadIdx.x;
    if (i >= 2 * nw4h) return;
    float4 v = (i < nw4h) ? reinterpret_cast<const float4*>(Wq)[i]
                          : reinterpret_cast<const float4*>(Wk)[i - nw4h];
    __half2 h0 = __floats2half2_rn(v.x, v.y);
    __half2 h1 = __floats2half2_rn(v.z, v.w);
    uint2 pk;
    pk.x = *reinterpret_cast<unsigned int*>(&h0);
    pk.y = *reinterpret_cast<unsigned int*>(&h1);
    *reinterpret_cast<uint2*>(g_wh + (size_t)i * 4) = pk;
}

// ---------------------------------------------------------------------------
// Async-copy / ldmatrix / mma helpers (baseline compute_103 PTX)
// ---------------------------------------------------------------------------
__device__ __forceinline__ void cp16(void* dst, const void* src, bool pred) {
    unsigned sa = (unsigned)__cvta_generic_to_shared(dst);
    int sz = pred ? 16 : 0;
    asm volatile("cp.async.cg.shared.global [%0], [%1], 16, %2;\n"
                 :: "r"(sa), "l"(src), "r"(sz));
}
__device__ __forceinline__ void cp_commit() { asm volatile("cp.async.commit_group;\n"); }
template <int W>
__device__ __forceinline__ void cp_wait() {
    asm volatile("cp.async.wait_group %0;\n" :: "n"(W));
}
__device__ __forceinline__ void ldsm_x4(uint32_t& r0, uint32_t& r1,
                                        uint32_t& r2, uint32_t& r3, uint32_t addr) {
    asm volatile("ldmatrix.sync.aligned.m8n8.x4.shared.b16 {%0,%1,%2,%3}, [%4];"
                 : "=r"(r0), "=r"(r1), "=r"(r2), "=r"(r3) : "r"(addr));
}
__device__ __forceinline__ void mma16816(float* c,
                                         uint32_t a0, uint32_t a1, uint32_t a2, uint32_t a3,
                                         uint32_t b0, uint32_t b1) {
    asm volatile("mma.sync.aligned.m16n8k16.row.col.f32.f16.f16.f32 "
                 "{%0,%1,%2,%3}, {%4,%5,%6,%7}, {%8,%9}, {%0,%1,%2,%3};"
                 : "+f"(c[0]), "+f"(c[1]), "+f"(c[2]), "+f"(c[3])
                 : "r"(a0), "r"(a1), "r"(a2), "r"(a3), "r"(b0), "r"(b1));
}

// ---------------------------------------------------------------------------
// Kernel 1: projection GEMM via mma.sync + ldmatrix, with FUSED x conversion.
//   qk[m][j] = sum_k x[m][k] * wh[j][k] + b[j]
// BM=128, BN=128, BK=32, 256 threads, 8 warps (2m x 4n), warp tile 64x32.
// A tile: fp32 LDG -> F2FP -> STS, register-prefetched one stage ahead
// (hidden under the HMMA issue bound). B tile: 2-stage cp.async from g_wh.
// ---------------------------------------------------------------------------
#define LDM 40
#define KIT (DDIM / 32)   // 8

__global__ __launch_bounds__(256)
void gemm_qk_mma(const float* __restrict__ x,
                 const float* __restrict__ bq,
                 const float* __restrict__ bk,
                 int N)
{
    __shared__ __align__(16) __half As[2][128][LDM];   // 20480 B
    __shared__ __align__(16) __half Bs[2][128][LDM];   // 20480 B
    __shared__ float bias_s[128];

    const int tid  = threadIdx.x;
    const int wid  = tid >> 5;
    const int lane = tid & 31;
    const int m0   = blockIdx.x * 128;
    const int n0   = blockIdx.y * 128;

    const int wm = wid & 1;           // m offset wm*64
    const int wn = wid >> 1;          // n offset wn*32

    if (tid < 128) {
        int gj = n0 + tid;
        bias_s[tid] = (gj < ADIM) ? bq[gj] : bk[gj - ADIM];
    }

    float c[4][4][4];                 // [m-frag][n8-frag][quad]
    #pragma unroll
    for (int i = 0; i < 4; i++)
        #pragma unroll
        for (int j = 0; j < 4; j++)
            #pragma unroll
            for (int q = 0; q < 4; q++) c[i][j][q] = 0.f;

    // staging map: row = tid>>1, 16-half chunk = (tid&1)*16
    const int srow = tid >> 1;            // 0..127
    const int scol = (tid & 1) * 16;      // halves: 0 or 16
    const int gm   = m0 + srow;
    const bool mok = gm < N;
    const float*  axsrc = x + (size_t)(mok ? gm : 0) * DDIM + scol;  // fp32 source
    const __half* bsrc  = g_wh + (size_t)(n0 + srow) * DDIM + scol;

    // ldmatrix per-lane base byte-offsets (within a stage)
    const uint32_t aoff = (uint32_t)(((wm * 64 + (lane & 15)) * LDM + (lane >> 4) * 8) * 2);
    const uint32_t boff = (uint32_t)(((wn * 32 + ((lane >> 3) & 1) * 8 + (lane & 7)) * LDM
                                      + (lane >> 4) * 8) * 2);
    const uint32_t smA0 = (uint32_t)__cvta_generic_to_shared(&As[0][0][0]);
    const uint32_t smB0 = (uint32_t)__cvta_generic_to_shared(&Bs[0][0][0]);
    const uint32_t stageSz = 128 * LDM * 2;

    // ---- A-tile register prefetch helpers ----
    float4 ar[4];                          // 16 fp32 = one 16-half chunk
    auto lda = [&](int k0) {
        if (mok) {
            ar[0] = *reinterpret_cast<const float4*>(axsrc + k0);
            ar[1] = *reinterpret_cast<const float4*>(axsrc + k0 + 4);
            ar[2] = *reinterpret_cast<const float4*>(axsrc + k0 + 8);
            ar[3] = *reinterpret_cast<const float4*>(axsrc + k0 + 12);
        } else {
            ar[0] = ar[1] = ar[2] = ar[3] = make_float4(0.f, 0.f, 0.f, 0.f);
        }
    };
    auto sta = [&](int buf) {
        __half hv[16];
        #pragma unroll
        for (int q = 0; q < 4; q++) {
            const float* f = reinterpret_cast<const float*>(&ar[q]);
            hv[q * 4 + 0] = __float2half(f[0]);
            hv[q * 4 + 1] = __float2half(f[1]);
            hv[q * 4 + 2] = __float2half(f[2]);
            hv[q * 4 + 3] = __float2half(f[3]);
        }
        uint4* dst = reinterpret_cast<uint4*>(&As[buf][srow][scol]);
        dst[0] = reinterpret_cast<const uint4*>(hv)[0];
        dst[1] = reinterpret_cast<const uint4*>(hv)[1];
    };

    // prologue: A stage0 direct; A stage1 held in regs; B stages 0,1 via cp.async
    lda(0);
    sta(0);
    #pragma unroll
    for (int s = 0; s < 2; s++) {
        const int k0 = s * 32;
        cp16(&Bs[s][srow][scol],     bsrc + k0,     true);
        cp16(&Bs[s][srow][scol + 8], bsrc + k0 + 8, true);
        cp_commit();
    }
    lda(32);

    #pragma unroll
    for (int it = 0; it < KIT; it++) {
        const int buf = it & 1;
        if (it == KIT - 1) cp_wait<0>(); else cp_wait<1>();
        __syncthreads();
        // As[buf^1] free (all reads finished before the sync above): store next A
        if (it + 1 < KIT) sta(buf ^ 1);

        const uint32_t abase = smA0 + buf * stageSz + aoff;
        const uint32_t bbase = smB0 + buf * stageSz + boff;

        #pragma unroll
        for (int ks = 0; ks < 32; ks += 16) {
            uint32_t a[4][4];
            #pragma unroll
            for (int i = 0; i < 4; i++)
                ldsm_x4(a[i][0], a[i][1], a[i][2], a[i][3],
                        abase + (uint32_t)((i * 16 * LDM + ks) * 2));
            uint32_t b0[4], b1[4];
            ldsm_x4(b0[0], b0[1], b0[2], b0[3], bbase + (uint32_t)(ks * 2));
            ldsm_x4(b1[0], b1[1], b1[2], b1[3], bbase + (uint32_t)((16 * LDM + ks) * 2));

            #pragma unroll
            for (int i = 0; i < 4; i++) {
                mma16816(c[i][0], a[i][0], a[i][1], a[i][2], a[i][3], b0[0], b0[2]);
                mma16816(c[i][1], a[i][0], a[i][1], a[i][2], a[i][3], b0[1], b0[3]);
                mma16816(c[i][2], a[i][0], a[i][1], a[i][2], a[i][3], b1[0], b1[2]);
                mma16816(c[i][3], a[i][0], a[i][1], a[i][2], a[i][3], b1[1], b1[3]);
            }
        }
        __syncthreads();

        const int kn = (it + 2) * 32;
        if (kn < DDIM) {
            // refill B (into the buffer just consumed) and A regs for it+2
            cp16(&Bs[buf][srow][scol],     bsrc + kn,     true);
            cp16(&Bs[buf][srow][scol + 8], bsrc + kn + 8, true);
            cp_commit();
            lda(kn);
        }
    }

    // epilogue: direct gmem stores with bias (half2 per fragment row)
    const int colq = (lane & 3) * 2;               // 0,2,4,6
    #pragma unroll
    for (int j = 0; j < 4; j++) {
        const int col = n0 + wn * 32 + j * 8 + colq;
        const float bx = bias_s[col - n0];
        const float by = bias_s[col - n0 + 1];
        #pragma unroll
        for (int i = 0; i < 4; i++) {
            const int r0 = m0 + wm * 64 + i * 16 + (lane >> 2);
            if (r0 < N) {
                __half2 h = __floats2half2_rn(c[i][j][0] + bx, c[i][j][1] + by);
                *reinterpret_cast<__half2*>(g_qk + (size_t)r0 * QKW + col) = h;
            }
            const int r1 = r0 + 8;
            if (r1 < N) {
                __half2 h = __floats2half2_rn(c[i][j][2] + bx, c[i][j][3] + by);
                *reinterpret_cast<__half2*>(g_qk + (size_t)r1 * QKW + col) = h;
            }
        }
    }
}

// ---------------------------------------------------------------------------
// Kernel 2: per-edge symmetric attention score + fused scatter-add.
// 8 lanes per edge, 4 edges per warp (at L2/LTS cap; unchanged).
// ---------------------------------------------------------------------------
__global__ __launch_bounds__(256)
void edge_kernel(const int* __restrict__ ei,
                 const int* __restrict__ d0r1,
                 float* __restrict__ out,
                 int N, int E)
{
    const int warp = (blockIdx.x * blockDim.x + threadIdx.x) >> 5;
    const int lane = threadIdx.x & 31;
    const int g    = lane >> 3;
    const int l    = lane & 7;
    const int e    = warp * 4 + g;
    if (e >= E) return;

    const int s = __ldg(ei + e);
    const int d = __ldg(ei + E + e);

    const uint4* rs = reinterpret_cast<const uint4*>(g_qk + (size_t)s * QKW);
    const uint4* rd = reinterpret_cast<const uint4*>(g_qk + (size_t)d * QKW);

    const uint4 a0 = rs[l];        const uint4 b0 = rd[16 + l];
    const uint4 a1 = rs[8 + l];    const uint4 b1 = rd[24 + l];
    const uint4 a2 = rd[l];        const uint4 b2 = rs[16 + l];
    const uint4 a3 = rd[8 + l];    const uint4 b3 = rs[24 + l];

    float p = 0.f;
    {
        const __half2* ah; const __half2* bh;
        #define DOT8(AV, BV)                                         \
            ah = reinterpret_cast<const __half2*>(&(AV));            \
            bh = reinterpret_cast<const __half2*>(&(BV));            \
            _Pragma("unroll")                                        \
            for (int i = 0; i < 4; i++) {                            \
                float2 fa = __half22float2(ah[i]);                   \
                float2 fb = __half22float2(bh[i]);                   \
                p = fmaf(fa.x, fb.x, p);                             \
                p = fmaf(fa.y, fb.y, p);                             \
            }
        DOT8(a0, b0)
        DOT8(a1, b1)
        DOT8(a2, b2)
        DOT8(a3, b3)
        #undef DOT8
    }

    p += __shfl_xor_sync(0xffffffffu, p, 4);
    p += __shfl_xor_sync(0xffffffffu, p, 2);
    p += __shfl_xor_sync(0xffffffffu, p, 1);

    if (l == 0) {
        const float v = __expf(p * 0.0625f);
        out[N + e] = v;
        int2 dp = *reinterpret_cast<const int2*>(d0r1 + 2 * e);
        atomicAdd(out + dp.x, v);
        atomicAdd(out + dp.y, v);
    }
}

// ---------------------------------------------------------------------------
extern "C" void kernel_launch(void* const* d_in, const int* in_sizes, int n_in,
                              void* d_out, int out_size)
{
    const float* x  = (const float*)d_in[0];
    const float* Wq = (const float*)d_in[1];
    const float* bq = (const float*)d_in[2];
    const float* Wk = (const float*)d_in[3];
    const float* bk = (const float*)d_in[4];
    const int*   ei = (const int*)d_in[5];
    const int*   d0 = (const int*)d_in[6];
    float* out = (float*)d_out;

    const int A    = in_sizes[2];             // 128
    const int Dd   = in_sizes[1] / A;         // 256
    const int N    = in_sizes[0] / Dd;        // 50000
    const int E    = in_sizes[5] / 2;         // 800000
    const int twoE = in_sizes[6] / 2;         // 2E
    (void)n_in; (void)out_size;

    cudaMemsetAsync(out, 0, (size_t)N * sizeof(float), 0);

    // fp16 W table (tiny)
    const int nw4h = A * Dd / 4;
    int wblocks = (2 * nw4h + 255) / 256;
    convert_w_kernel<<<wblocks, 256>>>(Wq, Wk, nw4h);

    // projection GEMM with fused x conversion
    dim3 ggrd((N + 127) / 128, QKW / 128);
    gemm_qk_mma<<<ggrd, 256>>>(x, bq, bk, N);

    // per-edge score + scatter
    int nwarps = (E + 3) / 4;
    int blocks = (nwarps + 7) / 8;
    edge_kernel<<<blocks, 256>>>(ei, d0 + twoE, out, N, E);
}